// round 12
// baseline (speedup 1.0000x reference)
#include <cuda_runtime.h>
#include <cstdint>

#define NB 8
#define CB 16
#define HB 256
#define WB 256
#define TOT (NB*CB*HB*WB)   // 8388608
#define IDX_OFF (TOT + 91)

#define TJ 64               // output tile width  (j)
#define TI 8                // output tile height (i)
#define NTHR 128            // 4 warps; warp w -> output rows 2w, 2w+1
#define PCOLS 68            // 66 used (TJ+2 halo), padded
#define PROWS (TI+2)        // 10
#define PSZ (PROWS*PCOLS)
#define NELEM (PROWS*66)    // 660 plane elements
#define KPT 6               // ceil(660/128) prefetch elems per thread
#define NBUF 10
#define SLOTS 512

__device__ float2 g_mm[SLOTS];   // per-block (min,max) partials

// ---------------------------------------------------------------------------
__global__ void __launch_bounds__(256)
minmax_kernel(const float4* __restrict__ x, int n4,
              const float* __restrict__ co,
              const float* __restrict__ filt,
              float* __restrict__ out) {
    if (blockIdx.x == 0) {
        int t = threadIdx.x;
        if (t < 64) out[TOT + t] = co[t];
        if (t < 27) out[TOT + 64 + t] = filt[t];
    }
    float lmin = __int_as_float(0x7f800000);
    float lmax = 0.0f;
    int stride = gridDim.x * blockDim.x;
    for (int i = blockIdx.x * blockDim.x + threadIdx.x; i < n4; i += stride) {
        float4 v = x[i];
        lmin = fminf(lmin, fminf(fminf(v.x, v.y), fminf(v.z, v.w)));
        lmax = fmaxf(lmax, fmaxf(fmaxf(v.x, v.y), fmaxf(v.z, v.w)));
    }
#pragma unroll
    for (int o = 16; o; o >>= 1) {
        lmin = fminf(lmin, __shfl_xor_sync(0xffffffffu, lmin, o));
        lmax = fmaxf(lmax, __shfl_xor_sync(0xffffffffu, lmax, o));
    }
    __shared__ float smin[8], smax[8];
    int w = threadIdx.x >> 5;
    if ((threadIdx.x & 31) == 0) { smin[w] = lmin; smax[w] = lmax; }
    __syncthreads();
    if (threadIdx.x < 8) {
        lmin = smin[threadIdx.x];
        lmax = smax[threadIdx.x];
#pragma unroll
        for (int o = 4; o; o >>= 1) {
            lmin = fminf(lmin, __shfl_xor_sync(0xffu, lmin, o));
            lmax = fmaxf(lmax, __shfl_xor_sync(0xffu, lmax, o));
        }
        if (threadIdx.x == 0) g_mm[blockIdx.x] = make_float2(lmin, lmax);
    }
}

// ---------------------------------------------------------------------------
__device__ __forceinline__ uint32_t smem_u32(const void* p) {
    uint32_t a;
    asm("{ .reg .u64 t; cvta.to.shared.u64 t, %1; cvt.u32.u64 %0, t; }"
        : "=r"(a) : "l"(p));
    return a;
}

// co gather: addr = (w & 0x380) | rbase -> one LOP3, then LDS (bank = lane).
__device__ __forceinline__ float co_gather(uint32_t w, uint32_t rbase) {
    uint32_t a; float v;
    asm("lop3.b32 %0, %1, 0x380, %2, 0xEA;" : "=r"(a) : "r"(w), "r"(rbase));
    asm("ld.shared.f32 %0, [%1];" : "=f"(v) : "r"(a));
    return v;
}

// ---------------------------------------------------------------------------
// out[n,c,i,j] = [idx_p<8] * sum_{27} filt * co[idx_p, clamp(idx_nbr,7)] * x_nbr
//
// Packed word: x mantissa bits [9:7] = clamped column (pre-shifted byte
// offset for the 128B column stride), bit [10] = (idx==8) flag.
// co table: 8 rows x 8 cols x 32 lane replicas (8 KB), conflict-free.
//
// KEY (this round): FOUR channels per iteration from planes ci-1..ci+4 in a
// 10-buffer ring. One __syncthreads + one LDG burst per 4 channels; each
// plane's 4 rows are loaded once per warp and reused by up to 3 channels.
// Ring safety: reads bufs base..base+5, writes base+6..base+9 (mod 10,
// disjoint); overwritten planes last read a full iteration earlier.
// ---------------------------------------------------------------------------
__global__ void __launch_bounds__(NTHR)
cooc_kernel(const float* __restrict__ x,
            const float* __restrict__ co,
            const float* __restrict__ filt,
            float* __restrict__ out) {
    __shared__ __align__(16) unsigned planes[NBUF][PSZ];  // ~26.6 KB
    __shared__ float co_pad[2048 + 256];                  // 8 KB + align pad
    __shared__ float s_red[16];
    __shared__ float s_mm[2];

    const int tid  = threadIdx.x;
    const int lane = tid & 31;
    const int wrp  = tid >> 5;

    const int j0 = blockIdx.x * TJ;
    const int i0 = blockIdx.y * TI;
    const int n  = blockIdx.z;

    // ---- reduce min/max partials ----
    {
        float2 a = g_mm[tid];
        float2 b = g_mm[tid + 128];
        float2 c = g_mm[tid + 256];
        float2 d = g_mm[tid + 384];
        float mn = fminf(fminf(a.x, b.x), fminf(c.x, d.x));
        float mx = fmaxf(fmaxf(a.y, b.y), fmaxf(c.y, d.y));
#pragma unroll
        for (int o = 16; o; o >>= 1) {
            mn = fminf(mn, __shfl_xor_sync(0xffffffffu, mn, o));
            mx = fmaxf(mx, __shfl_xor_sync(0xffffffffu, mx, o));
        }
        if (lane == 0) { s_red[wrp] = mn; s_red[8 + wrp] = mx; }
    }

    // ---- replicated co LUT ----
    uintptr_t gp = (uintptr_t)co_pad;
    float* co_rep = (float*)((gp + 1023) & ~(uintptr_t)1023);
    const uint32_t co_u32 = smem_u32(co_rep);
    for (int e = tid; e < 2048; e += NTHR) {
        int l = e & 31;
        int c = (e >> 5) & 7;
        int r = e >> 8;
        co_rep[r * 256 + c * 32 + l] = co[r * 8 + c];
    }

    // ---- filter -> registers (fenced) ----
    float fr[27];
#pragma unroll
    for (int k = 0; k < 27; k++) {
        float v = filt[k];
        asm("mov.f32 %0, %0;" : "+f"(v));
        fr[k] = v;
    }

    __syncthreads();
    if (tid < 2) {
        float v;
        if (tid == 0) v = fminf(fminf(s_red[0], s_red[1]), fminf(s_red[2], s_red[3]));
        else          v = fmaxf(fmaxf(s_red[8], s_red[9]), fmaxf(s_red[10], s_red[11]));
        s_mm[tid] = v;
    }
    __syncthreads();
    const float xmin = s_mm[0];
    const float xmax = s_mm[1];

    const float* xb = x + (size_t)n * (CB * HB * WB);

    auto pack = [&](float xv) -> unsigned {
        float t = __fdiv_rn(xv - xmin, xmax) * 8.0f;   // exact JAX rounding
        int q = (int)t;                                 // [0, 8]
        unsigned qc = (q < 8) ? (unsigned)q : 7u;
        unsigned fl = (q >= 8) ? 1u : 0u;
        return (__float_as_uint(xv) & ~0x780u) | (qc << 7) | (fl << 10);
    };

    // ---- channel-invariant prefetch geometry ----
    int  goff[KPT];
    int  soff[KPT];
    bool evalid[KPT];
#pragma unroll
    for (int k = 0; k < KPT; k++) {
        int e = tid + 128 * k;
        int r = e / 66;
        int c = e - r * 66;
        int gi = i0 - 1 + r;
        int gj = j0 - 1 + c;
        bool ok = (e < NELEM) && ((unsigned)gi < (unsigned)HB) &&
                  ((unsigned)gj < (unsigned)WB);
        goff[k]   = ok ? (gi * WB + gj) : 0;
        soff[k]   = r * PCOLS + c;
        evalid[k] = ok;
    }

    auto load_plane = [&](int cc, int buf) {
        unsigned* B = planes[buf];
        if ((unsigned)cc < (unsigned)CB) {
            const float* src = xb + cc * (HB * WB);
#pragma unroll
            for (int k = 0; k < KPT; k++) {
                if (tid + 128 * k < NELEM) {
                    unsigned pv = evalid[k] ? pack(src[goff[k]]) : 0u;
                    B[soff[k]] = pv;
                }
            }
        } else {
#pragma unroll
            for (int k = 0; k < KPT; k++)
                if (tid + 128 * k < NELEM) B[soff[k]] = 0u;
        }
    };

    // prologue: planes -1..4 -> bufs 0..5  (plane p -> buf (p+1) mod 10)
    load_plane(-1, 0);
    load_plane(0, 1);
    load_plane(1, 2);
    load_plane(2, 3);
    load_plane(3, 4);
    load_plane(4, 5);

    const int rowbase = 2 * wrp;
    const int gi0     = i0 + 2 * wrp;
    const int jb      = j0 + 2 * lane;
    const uint32_t lanebase = co_u32 + (lane << 2);

    auto tap3 = [&](float& acc, uint32_t rb, int fo,
                    unsigned p0, unsigned p1, unsigned p2) {
        acc = fmaf(fr[fo + 0], co_gather(p0, rb) * __uint_as_float(p0), acc);
        acc = fmaf(fr[fo + 1], co_gather(p1, rb) * __uint_as_float(p1), acc);
        acc = fmaf(fr[fo + 2], co_gather(p2, rb) * __uint_as_float(p2), acc);
    };

    int base = 0;   // buf of plane ci-1  ( = (4*it) mod 10 )
    for (int it = 0; it < CB / 4; it++) {
        const int ci = 4 * it;
        __syncthreads();

        // ---- prefetch planes ci+5..ci+8 into bufs base+6..base+9 ----
        if (it < CB / 4 - 1) {
#pragma unroll
            for (int q = 0; q < 4; q++) {
                int b = base + 6 + q; if (b >= NBUF) b -= NBUF;
                load_plane(ci + 5 + q, b);
            }
        }

        // ---- centers for the 4 channels ----
        unsigned cw[4][4];
        uint32_t rb[4][4];
#pragma unroll
        for (int k = 0; k < 4; k++) {
            int b = base + 1 + k; if (b >= NBUF) b -= NBUF;
            const unsigned* Pc = planes[b] + rowbase * PCOLS + 2 * lane;
            uint2 c1  = *(const uint2*)(Pc + 1 * PCOLS);
            uint2 c1h = *(const uint2*)(Pc + 1 * PCOLS + 2);
            uint2 c2  = *(const uint2*)(Pc + 2 * PCOLS);
            uint2 c2h = *(const uint2*)(Pc + 2 * PCOLS + 2);
            cw[k][0] = c1.y;  cw[k][1] = c1h.x;
            cw[k][2] = c2.y;  cw[k][3] = c2h.x;
#pragma unroll
            for (int u = 0; u < 4; u++)
                rb[k][u] = lanebase + ((cw[k][u] & 0x380u) << 3);
        }

        float acc[4][4];
#pragma unroll
        for (int k = 0; k < 4; k++)
#pragma unroll
            for (int u = 0; u < 4; u++) acc[k][u] = 0.0f;

        // ---- taps: 6 planes, rows loaded once, reused by <=3 channels ----
#pragma unroll
        for (int pi = 0; pi < 6; pi++) {
            int bp = base + pi; if (bp >= NBUF) bp -= NBUF;
            const unsigned* P = planes[bp] + rowbase * PCOLS + 2 * lane;
#pragma unroll
            for (int r = 0; r < 4; r++) {
                uint2 A  = *(const uint2*)(P + r * PCOLS);
                uint2 Bv = *(const uint2*)(P + r * PCOLS + 2);
                unsigned w0 = A.x, w1 = A.y, w2 = Bv.x, w3 = Bv.y;
#pragma unroll
                for (int k = 0; k < 4; k++) {
                    const int dc = pi - k;
                    if (dc >= 0 && dc <= 2) {
                        if (r <= 2) {
                            tap3(acc[k][0], rb[k][0], dc * 9 + r * 3, w0, w1, w2);
                            tap3(acc[k][1], rb[k][1], dc * 9 + r * 3, w1, w2, w3);
                        }
                        if (r >= 1) {
                            tap3(acc[k][2], rb[k][2], dc * 9 + (r - 1) * 3, w0, w1, w2);
                            tap3(acc[k][3], rb[k][3], dc * 9 + (r - 1) * 3, w1, w2, w3);
                        }
                    }
                }
            }
        }

        // ---- stores ----
#pragma unroll
        for (int k = 0; k < 4; k++) {
            const int o0 = ((n * CB + ci + k) * HB + gi0) * WB + jb;
            const int o1 = o0 + WB;
            float2 r0v, r1v;
            r0v.x = (cw[k][0] & 0x400u) ? 0.0f : acc[k][0];
            r0v.y = (cw[k][1] & 0x400u) ? 0.0f : acc[k][1];
            r1v.x = (cw[k][2] & 0x400u) ? 0.0f : acc[k][2];
            r1v.y = (cw[k][3] & 0x400u) ? 0.0f : acc[k][3];
            *(float2*)(out + o0) = r0v;
            *(float2*)(out + o1) = r1v;
            out[IDX_OFF + o0]     = (float)(((cw[k][0] >> 7) & 7u) + ((cw[k][0] >> 10) & 1u));
            out[IDX_OFF + o0 + 1] = (float)(((cw[k][1] >> 7) & 7u) + ((cw[k][1] >> 10) & 1u));
            out[IDX_OFF + o1]     = (float)(((cw[k][2] >> 7) & 7u) + ((cw[k][2] >> 10) & 1u));
            out[IDX_OFF + o1 + 1] = (float)(((cw[k][3] >> 7) & 7u) + ((cw[k][3] >> 10) & 1u));
        }

        base += 4; if (base >= NBUF) base -= NBUF;
    }
}

// ---------------------------------------------------------------------------
extern "C" void kernel_launch(void* const* d_in, const int* in_sizes, int n_in,
                              void* d_out, int out_size) {
    const float* x    = (const float*)d_in[0];
    const float* co   = (const float*)d_in[1];
    const float* filt = (const float*)d_in[2];
    float* out        = (float*)d_out;

    minmax_kernel<<<SLOTS, 256>>>((const float4*)x, TOT / 4, co, filt, out);

    dim3 grid(WB / TJ, HB / TI, NB);   // 4 x 32 x 8 = 1024 blocks
    cooc_kernel<<<grid, NTHR>>>(x, co, filt, out);
}

// round 13
// speedup vs baseline: 1.5553x; 1.5553x over previous
#include <cuda_runtime.h>
#include <cstdint>

#define NB 8
#define CB 16
#define HB 256
#define WB 256
#define TOT (NB*CB*HB*WB)   // 8388608
#define IDX_OFF (TOT + 91)

#define TJ 64               // output tile width  (j)
#define TI 8                // output tile height (i)
#define NTHR 128            // 4 warps; warp w -> output rows 2w, 2w+1
#define PCOLS 68            // 66 used (TJ+2 halo), padded
#define PROWS (TI+2)        // 10
#define PSZ (PROWS*PCOLS)
#define NELEM (PROWS*66)    // 660 plane elements
#define KPT 6               // ceil(660/128) prefetch elems per thread
#define NBUF 7
#define SLOTS 512

__device__ float2 g_mm[SLOTS];   // per-block (min,max) partials

// ---------------------------------------------------------------------------
__global__ void __launch_bounds__(256)
minmax_kernel(const float4* __restrict__ x, int n4,
              const float* __restrict__ co,
              const float* __restrict__ filt,
              float* __restrict__ out) {
    if (blockIdx.x == 0) {
        int t = threadIdx.x;
        if (t < 64) out[TOT + t] = co[t];
        if (t < 27) out[TOT + 64 + t] = filt[t];
    }
    float lmin = __int_as_float(0x7f800000);
    float lmax = 0.0f;
    int stride = gridDim.x * blockDim.x;
    for (int i = blockIdx.x * blockDim.x + threadIdx.x; i < n4; i += stride) {
        float4 v = x[i];
        lmin = fminf(lmin, fminf(fminf(v.x, v.y), fminf(v.z, v.w)));
        lmax = fmaxf(lmax, fmaxf(fmaxf(v.x, v.y), fmaxf(v.z, v.w)));
    }
#pragma unroll
    for (int o = 16; o; o >>= 1) {
        lmin = fminf(lmin, __shfl_xor_sync(0xffffffffu, lmin, o));
        lmax = fmaxf(lmax, __shfl_xor_sync(0xffffffffu, lmax, o));
    }
    __shared__ float smin[8], smax[8];
    int w = threadIdx.x >> 5;
    if ((threadIdx.x & 31) == 0) { smin[w] = lmin; smax[w] = lmax; }
    __syncthreads();
    if (threadIdx.x < 8) {
        lmin = smin[threadIdx.x];
        lmax = smax[threadIdx.x];
#pragma unroll
        for (int o = 4; o; o >>= 1) {
            lmin = fminf(lmin, __shfl_xor_sync(0xffu, lmin, o));
            lmax = fmaxf(lmax, __shfl_xor_sync(0xffu, lmax, o));
        }
        if (threadIdx.x == 0) g_mm[blockIdx.x] = make_float2(lmin, lmax);
    }
}

// ---------------------------------------------------------------------------
__device__ __forceinline__ uint32_t smem_u32(const void* p) {
    uint32_t a;
    asm("{ .reg .u64 t; cvta.to.shared.u64 t, %1; cvt.u32.u64 %0, t; }"
        : "=r"(a) : "l"(p));
    return a;
}

// co gather: addr = (w & 0x380) | rbase -> one LOP3, then LDS (bank = lane).
__device__ __forceinline__ float co_gather(uint32_t w, uint32_t rbase) {
    uint32_t a; float v;
    asm("lop3.b32 %0, %1, 0x380, %2, 0xEA;" : "=r"(a) : "r"(w), "r"(rbase));
    asm("ld.shared.f32 %0, [%1];" : "=f"(v) : "r"(a));
    return v;
}

// ---------------------------------------------------------------------------
// out[n,c,i,j] = [idx_p<8] * sum_{27} filt * co[idx_p, clamp(idx_nbr,7)] * x_nbr
//
// Packed word: x mantissa bits [9:7] = clamped column (pre-shifted byte
// offset for the 128B column stride), bit [10] = (idx==8) flag.
// co table: 8 rows x 8 cols x 32 lane replicas (8 KB), conflict-free.
//
// Structure: TWO channels per iteration, 7-buffer plane ring (R11 base,
// best measured).  NEW: the two next planes' LDGs are STAGED INTO REGISTERS
// right after the sync with no consumer, the 2-channel compute (~840 instrs)
// runs while they are in flight, and pack+STS happen at the end of the
// iteration.  This removes the block-wide ~600-cycle stall that pinned
// issue at 59% when pack consumed the LDG immediately.
// Ring safety: reads bufs base..base+3; late writes hit base+4, base+5,
// which nothing reads until after the next top-of-iteration sync.
// ---------------------------------------------------------------------------
__global__ void __launch_bounds__(NTHR)
cooc_kernel(const float* __restrict__ x,
            const float* __restrict__ co,
            const float* __restrict__ filt,
            float* __restrict__ out) {
    __shared__ __align__(16) unsigned planes[NBUF][PSZ];  // ~18.6 KB
    __shared__ float co_pad[2048 + 256];                  // 8 KB + align pad
    __shared__ float s_red[16];
    __shared__ float s_mm[2];

    const int tid  = threadIdx.x;
    const int lane = tid & 31;
    const int wrp  = tid >> 5;

    const int j0 = blockIdx.x * TJ;
    const int i0 = blockIdx.y * TI;
    const int n  = blockIdx.z;

    // ---- reduce min/max partials ----
    {
        float2 a = g_mm[tid];
        float2 b = g_mm[tid + 128];
        float2 c = g_mm[tid + 256];
        float2 d = g_mm[tid + 384];
        float mn = fminf(fminf(a.x, b.x), fminf(c.x, d.x));
        float mx = fmaxf(fmaxf(a.y, b.y), fmaxf(c.y, d.y));
#pragma unroll
        for (int o = 16; o; o >>= 1) {
            mn = fminf(mn, __shfl_xor_sync(0xffffffffu, mn, o));
            mx = fmaxf(mx, __shfl_xor_sync(0xffffffffu, mx, o));
        }
        if (lane == 0) { s_red[wrp] = mn; s_red[8 + wrp] = mx; }
    }

    // ---- replicated co LUT ----
    uintptr_t gp = (uintptr_t)co_pad;
    float* co_rep = (float*)((gp + 1023) & ~(uintptr_t)1023);
    const uint32_t co_u32 = smem_u32(co_rep);
    for (int e = tid; e < 2048; e += NTHR) {
        int l = e & 31;
        int c = (e >> 5) & 7;
        int r = e >> 8;
        co_rep[r * 256 + c * 32 + l] = co[r * 8 + c];
    }

    // ---- filter -> registers (fenced) ----
    float fr[27];
#pragma unroll
    for (int k = 0; k < 27; k++) {
        float v = filt[k];
        asm("mov.f32 %0, %0;" : "+f"(v));
        fr[k] = v;
    }

    __syncthreads();
    if (tid < 2) {
        float v;
        if (tid == 0) v = fminf(fminf(s_red[0], s_red[1]), fminf(s_red[2], s_red[3]));
        else          v = fmaxf(fmaxf(s_red[8], s_red[9]), fmaxf(s_red[10], s_red[11]));
        s_mm[tid] = v;
    }
    __syncthreads();
    const float xmin = s_mm[0];
    const float xmax = s_mm[1];

    const float* xb = x + (size_t)n * (CB * HB * WB);

    auto pack = [&](float xv) -> unsigned {
        float t = __fdiv_rn(xv - xmin, xmax) * 8.0f;   // exact JAX rounding
        int q = (int)t;                                 // [0, 8]
        unsigned qc = (q < 8) ? (unsigned)q : 7u;
        unsigned fl = (q >= 8) ? 1u : 0u;
        return (__float_as_uint(xv) & ~0x780u) | (qc << 7) | (fl << 10);
    };

    // ---- channel-invariant prefetch geometry ----
    int  goff[KPT];
    int  soff[KPT];
    bool evalid[KPT];
#pragma unroll
    for (int k = 0; k < KPT; k++) {
        int e = tid + 128 * k;
        int r = e / 66;
        int c = e - r * 66;
        int gi = i0 - 1 + r;
        int gj = j0 - 1 + c;
        bool ok = (e < NELEM) && ((unsigned)gi < (unsigned)HB) &&
                  ((unsigned)gj < (unsigned)WB);
        goff[k]   = ok ? (gi * WB + gj) : 0;
        soff[k]   = r * PCOLS + c;
        evalid[k] = ok;
    }

    auto load_plane = [&](int cc, int buf) {   // prologue only
        unsigned* B = planes[buf];
        if ((unsigned)cc < (unsigned)CB) {
            const float* src = xb + cc * (HB * WB);
#pragma unroll
            for (int k = 0; k < KPT; k++) {
                if (tid + 128 * k < NELEM)
                    B[soff[k]] = evalid[k] ? pack(src[goff[k]]) : 0u;
            }
        } else {
#pragma unroll
            for (int k = 0; k < KPT; k++)
                if (tid + 128 * k < NELEM) B[soff[k]] = 0u;
        }
    };

    // prologue: planes -1,0,1,2 -> bufs 0..3  (plane p -> buf (p+1) mod 7)
    load_plane(-1, 0);
    load_plane(0, 1);
    load_plane(1, 2);
    load_plane(2, 3);

    const int rowbase = 2 * wrp;
    const int gi0     = i0 + 2 * wrp;
    const int jb      = j0 + 2 * lane;
    const uint32_t lanebase = co_u32 + (lane << 2);

    auto tap3 = [&](float& acc, uint32_t rb, int fo,
                    unsigned p0, unsigned p1, unsigned p2) {
        acc = fmaf(fr[fo + 0], co_gather(p0, rb) * __uint_as_float(p0), acc);
        acc = fmaf(fr[fo + 1], co_gather(p1, rb) * __uint_as_float(p1), acc);
        acc = fmaf(fr[fo + 2], co_gather(p2, rb) * __uint_as_float(p2), acc);
    };

    int base = 0;   // buf index of plane ci-1  ( = ci mod 7 )
    for (int it = 0; it < CB / 2; it++) {
        const int ci = 2 * it;
        __syncthreads();

        // ---- stage LDGs for planes ci+3, ci+4 (no consumer until drain) ----
        float sv0[KPT], sv1[KPT];
        const bool do_pref = (it < CB / 2 - 1);
        if (do_pref) {
            const float* s0 = xb + (ci + 3) * (HB * WB);   // ci+3 <= 15 always
#pragma unroll
            for (int k = 0; k < KPT; k++)
                sv0[k] = evalid[k] ? s0[goff[k]] : 0.0f;
            if (ci + 4 < CB) {
                const float* s1 = xb + (ci + 4) * (HB * WB);
#pragma unroll
                for (int k = 0; k < KPT; k++)
                    sv1[k] = evalid[k] ? s1[goff[k]] : 0.0f;
            }
        }

        int bA = base + 1; if (bA >= NBUF) bA -= NBUF;   // plane ci
        int bB = base + 2; if (bB >= NBUF) bB -= NBUF;   // plane ci+1

        // ---- centers for both channels ----
        const unsigned* Pa = planes[bA] + rowbase * PCOLS + 2 * lane;
        const unsigned* Pb = planes[bB] + rowbase * PCOLS + 2 * lane;
        uint2 a1  = *(const uint2*)(Pa + 1 * PCOLS);
        uint2 a1h = *(const uint2*)(Pa + 1 * PCOLS + 2);
        uint2 a2  = *(const uint2*)(Pa + 2 * PCOLS);
        uint2 a2h = *(const uint2*)(Pa + 2 * PCOLS + 2);
        uint2 b1  = *(const uint2*)(Pb + 1 * PCOLS);
        uint2 b1h = *(const uint2*)(Pb + 1 * PCOLS + 2);
        uint2 b2  = *(const uint2*)(Pb + 2 * PCOLS);
        uint2 b2h = *(const uint2*)(Pb + 2 * PCOLS + 2);
        const unsigned cw00 = a1.y, cw01 = a1h.x, cw10 = a2.y, cw11 = a2h.x;
        const unsigned dw00 = b1.y, dw01 = b1h.x, dw10 = b2.y, dw11 = b2h.x;
        const uint32_t rb00 = lanebase + ((cw00 & 0x380u) << 3);
        const uint32_t rb01 = lanebase + ((cw01 & 0x380u) << 3);
        const uint32_t rb10 = lanebase + ((cw10 & 0x380u) << 3);
        const uint32_t rb11 = lanebase + ((cw11 & 0x380u) << 3);
        const uint32_t sb00 = lanebase + ((dw00 & 0x380u) << 3);
        const uint32_t sb01 = lanebase + ((dw01 & 0x380u) << 3);
        const uint32_t sb10 = lanebase + ((dw10 & 0x380u) << 3);
        const uint32_t sb11 = lanebase + ((dw11 & 0x380u) << 3);

        float a00 = 0.f, a01 = 0.f, a10 = 0.f, a11 = 0.f;   // channel ci
        float b00 = 0.f, b01 = 0.f, b10 = 0.f, b11 = 0.f;   // channel ci+1

#pragma unroll
        for (int pi = 0; pi < 4; pi++) {      // plane ci-1+pi
            int bp = base + pi; if (bp >= NBUF) bp -= NBUF;
            const unsigned* P = planes[bp] + rowbase * PCOLS + 2 * lane;
#pragma unroll
            for (int r = 0; r < 4; r++) {
                uint2 A  = *(const uint2*)(P + r * PCOLS);
                uint2 Bv = *(const uint2*)(P + r * PCOLS + 2);
                unsigned w0 = A.x, w1 = A.y, w2 = Bv.x, w3 = Bv.y;
                if (pi <= 2) {                 // channel ci, dc = pi
                    if (r <= 2) {
                        tap3(a00, rb00, pi * 9 + r * 3, w0, w1, w2);
                        tap3(a01, rb01, pi * 9 + r * 3, w1, w2, w3);
                    }
                    if (r >= 1) {
                        tap3(a10, rb10, pi * 9 + (r - 1) * 3, w0, w1, w2);
                        tap3(a11, rb11, pi * 9 + (r - 1) * 3, w1, w2, w3);
                    }
                }
                if (pi >= 1) {                 // channel ci+1, dc = pi-1
                    if (r <= 2) {
                        tap3(b00, sb00, (pi - 1) * 9 + r * 3, w0, w1, w2);
                        tap3(b01, sb01, (pi - 1) * 9 + r * 3, w1, w2, w3);
                    }
                    if (r >= 1) {
                        tap3(b10, sb10, (pi - 1) * 9 + (r - 1) * 3, w0, w1, w2);
                        tap3(b11, sb11, (pi - 1) * 9 + (r - 1) * 3, w1, w2, w3);
                    }
                }
            }
        }

        // ---- stores: channel ci ----
        const int o0 = ((n * CB + ci) * HB + gi0) * WB + jb;
        const int o1 = o0 + WB;
        {
            float2 r0v, r1v;
            r0v.x = (cw00 & 0x400u) ? 0.0f : a00;
            r0v.y = (cw01 & 0x400u) ? 0.0f : a01;
            r1v.x = (cw10 & 0x400u) ? 0.0f : a10;
            r1v.y = (cw11 & 0x400u) ? 0.0f : a11;
            *(float2*)(out + o0) = r0v;
            *(float2*)(out + o1) = r1v;
            out[IDX_OFF + o0]     = (float)(((cw00 >> 7) & 7u) + ((cw00 >> 10) & 1u));
            out[IDX_OFF + o0 + 1] = (float)(((cw01 >> 7) & 7u) + ((cw01 >> 10) & 1u));
            out[IDX_OFF + o1]     = (float)(((cw10 >> 7) & 7u) + ((cw10 >> 10) & 1u));
            out[IDX_OFF + o1 + 1] = (float)(((cw11 >> 7) & 7u) + ((cw11 >> 10) & 1u));
        }
        // ---- stores: channel ci+1 ----
        const int p0 = o0 + HB * WB;
        const int p1 = p0 + WB;
        {
            float2 r0v, r1v;
            r0v.x = (dw00 & 0x400u) ? 0.0f : b00;
            r0v.y = (dw01 & 0x400u) ? 0.0f : b01;
            r1v.x = (dw10 & 0x400u) ? 0.0f : b10;
            r1v.y = (dw11 & 0x400u) ? 0.0f : b11;
            *(float2*)(out + p0) = r0v;
            *(float2*)(out + p1) = r1v;
            out[IDX_OFF + p0]     = (float)(((dw00 >> 7) & 7u) + ((dw00 >> 10) & 1u));
            out[IDX_OFF + p0 + 1] = (float)(((dw01 >> 7) & 7u) + ((dw01 >> 10) & 1u));
            out[IDX_OFF + p1]     = (float)(((dw10 >> 7) & 7u) + ((dw10 >> 10) & 1u));
            out[IDX_OFF + p1 + 1] = (float)(((dw11 >> 7) & 7u) + ((dw11 >> 10) & 1u));
        }

        // ---- drain: pack staged values, store planes ci+3, ci+4 ----
        // writes hit bufs base+4, base+5: not read this iteration; next
        // iteration's reads happen after its top-of-loop __syncthreads.
        if (do_pref) {
            int b4 = base + 4; if (b4 >= NBUF) b4 -= NBUF;
            int b5 = base + 5; if (b5 >= NBUF) b5 -= NBUF;
            unsigned* B4 = planes[b4];
            unsigned* B5 = planes[b5];
            const bool in1 = (ci + 4 < CB);
#pragma unroll
            for (int k = 0; k < KPT; k++) {
                if (tid + 128 * k < NELEM) {
                    B4[soff[k]] = evalid[k] ? pack(sv0[k]) : 0u;
                    B5[soff[k]] = (in1 && evalid[k]) ? pack(sv1[k]) : 0u;
                }
            }
        }

        base += 2; if (base >= NBUF) base -= NBUF;
    }
}

// ---------------------------------------------------------------------------
extern "C" void kernel_launch(void* const* d_in, const int* in_sizes, int n_in,
                              void* d_out, int out_size) {
    const float* x    = (const float*)d_in[0];
    const float* co   = (const float*)d_in[1];
    const float* filt = (const float*)d_in[2];
    float* out        = (float*)d_out;

    minmax_kernel<<<SLOTS, 256>>>((const float4*)x, TOT / 4, co, filt, out);

    dim3 grid(WB / TJ, HB / TI, NB);   // 4 x 32 x 8 = 1024 blocks
    cooc_kernel<<<grid, NTHR>>>(x, co, filt, out);
}

// round 14
// speedup vs baseline: 1.6832x; 1.0823x over previous
#include <cuda_runtime.h>
#include <cstdint>

#define NB 8
#define CB 16
#define HB 256
#define WB 256
#define TOT (NB*CB*HB*WB)   // 8388608
#define IDX_OFF (TOT + 91)

#define TJ 64               // output tile width  (j)
#define TI 8                // output tile height (i)
#define NTHR 128            // 4 warps; warp w -> output rows 2w, 2w+1
#define PCOLS 68            // 66 used (TJ+2 halo), padded
#define PROWS (TI+2)        // 10
#define PSZ (PROWS*PCOLS)
#define NELEM (PROWS*66)    // 660 plane elements
#define KPT 6               // ceil(660/128) prefetch elems per thread
#define NBUF 8              // power of two -> ring index is & 7
#define SLOTS 512

__device__ float2 g_mm[SLOTS];   // per-block (min,max) partials

// ---------------------------------------------------------------------------
__global__ void __launch_bounds__(256)
minmax_kernel(const float4* __restrict__ x, int n4,
              const float* __restrict__ co,
              const float* __restrict__ filt,
              float* __restrict__ out) {
    if (blockIdx.x == 0) {
        int t = threadIdx.x;
        if (t < 64) out[TOT + t] = co[t];
        if (t < 27) out[TOT + 64 + t] = filt[t];
    }
    float lmin = __int_as_float(0x7f800000);
    float lmax = 0.0f;
    int stride = gridDim.x * blockDim.x;
    for (int i = blockIdx.x * blockDim.x + threadIdx.x; i < n4; i += stride) {
        float4 v = x[i];
        lmin = fminf(lmin, fminf(fminf(v.x, v.y), fminf(v.z, v.w)));
        lmax = fmaxf(lmax, fmaxf(fmaxf(v.x, v.y), fmaxf(v.z, v.w)));
    }
#pragma unroll
    for (int o = 16; o; o >>= 1) {
        lmin = fminf(lmin, __shfl_xor_sync(0xffffffffu, lmin, o));
        lmax = fmaxf(lmax, __shfl_xor_sync(0xffffffffu, lmax, o));
    }
    __shared__ float smin[8], smax[8];
    int w = threadIdx.x >> 5;
    if ((threadIdx.x & 31) == 0) { smin[w] = lmin; smax[w] = lmax; }
    __syncthreads();
    if (threadIdx.x < 8) {
        lmin = smin[threadIdx.x];
        lmax = smax[threadIdx.x];
#pragma unroll
        for (int o = 4; o; o >>= 1) {
            lmin = fminf(lmin, __shfl_xor_sync(0xffu, lmin, o));
            lmax = fmaxf(lmax, __shfl_xor_sync(0xffu, lmax, o));
        }
        if (threadIdx.x == 0) g_mm[blockIdx.x] = make_float2(lmin, lmax);
    }
}

// ---------------------------------------------------------------------------
__device__ __forceinline__ uint32_t smem_u32(const void* p) {
    uint32_t a;
    asm("{ .reg .u64 t; cvta.to.shared.u64 t, %1; cvt.u32.u64 %0, t; }"
        : "=r"(a) : "l"(p));
    return a;
}

// co gather: addr = (w & 0x380) | rbase -> one LOP3, then LDS (bank = lane).
__device__ __forceinline__ float co_gather(uint32_t w, uint32_t rbase) {
    uint32_t a; float v;
    asm("lop3.b32 %0, %1, 0x380, %2, 0xEA;" : "=r"(a) : "r"(w), "r"(rbase));
    asm("ld.shared.f32 %0, [%1];" : "=f"(v) : "r"(a));
    return v;
}

// ---------------------------------------------------------------------------
// out[n,c,i,j] = [idx_p<8] * sum_{27} filt * co[idx_p, clamp(idx_nbr,7)] * x_nbr
//
// Packed word: x mantissa bits [9:7] = clamped column (pre-shifted byte
// offset for the 128B column stride), bit [10] = (idx==8) flag.
// co table: 8 rows x 8 cols x 32 lane replicas (8 KB), conflict-free.
//
// Structure (R13 base, best measured): TWO channels per iteration, plane
// ring (now 8 bufs, & mask), staged-register LDGs hide global latency under
// the 2-channel compute.
// NEW: quantization division uses the Markstein exactly-rounded sequence
// with the block-invariant divisor xmax:  r = RN(1/xmax) once, then
// q0 = d*r; e = fma(-xmax, q0, d); q = fma(e, r, q0)  ==  fdiv_rn(d, xmax)
// (correctly rounded for normal operands) -> ~6 fewer instrs per pack,
// bit-identical idx.
// ---------------------------------------------------------------------------
__global__ void __launch_bounds__(NTHR)
cooc_kernel(const float* __restrict__ x,
            const float* __restrict__ co,
            const float* __restrict__ filt,
            float* __restrict__ out) {
    __shared__ __align__(16) unsigned planes[NBUF][PSZ];  // ~21.3 KB
    __shared__ float co_pad[2048 + 256];                  // 8 KB + align pad
    __shared__ float s_red[16];
    __shared__ float s_mm[2];

    const int tid  = threadIdx.x;
    const int lane = tid & 31;
    const int wrp  = tid >> 5;

    const int j0 = blockIdx.x * TJ;
    const int i0 = blockIdx.y * TI;
    const int n  = blockIdx.z;

    // ---- reduce min/max partials ----
    {
        float2 a = g_mm[tid];
        float2 b = g_mm[tid + 128];
        float2 c = g_mm[tid + 256];
        float2 d = g_mm[tid + 384];
        float mn = fminf(fminf(a.x, b.x), fminf(c.x, d.x));
        float mx = fmaxf(fmaxf(a.y, b.y), fmaxf(c.y, d.y));
#pragma unroll
        for (int o = 16; o; o >>= 1) {
            mn = fminf(mn, __shfl_xor_sync(0xffffffffu, mn, o));
            mx = fmaxf(mx, __shfl_xor_sync(0xffffffffu, mx, o));
        }
        if (lane == 0) { s_red[wrp] = mn; s_red[8 + wrp] = mx; }
    }

    // ---- replicated co LUT ----
    uintptr_t gp = (uintptr_t)co_pad;
    float* co_rep = (float*)((gp + 1023) & ~(uintptr_t)1023);
    const uint32_t co_u32 = smem_u32(co_rep);
    for (int e = tid; e < 2048; e += NTHR) {
        int l = e & 31;
        int c = (e >> 5) & 7;
        int r = e >> 8;
        co_rep[r * 256 + c * 32 + l] = co[r * 8 + c];
    }

    // ---- filter -> registers (fenced) ----
    float fr[27];
#pragma unroll
    for (int k = 0; k < 27; k++) {
        float v = filt[k];
        asm("mov.f32 %0, %0;" : "+f"(v));
        fr[k] = v;
    }

    __syncthreads();
    if (tid < 2) {
        float v;
        if (tid == 0) v = fminf(fminf(s_red[0], s_red[1]), fminf(s_red[2], s_red[3]));
        else          v = fmaxf(fmaxf(s_red[8], s_red[9]), fmaxf(s_red[10], s_red[11]));
        s_mm[tid] = v;
    }
    __syncthreads();
    const float xmin = s_mm[0];
    const float xmax = s_mm[1];
    const float rcpm = __frcp_rn(xmax);   // RN(1/xmax), once per thread

    const float* xb = x + (size_t)n * (CB * HB * WB);

    auto pack = [&](float xv) -> unsigned {
        // exactly-rounded (x - xmin)/xmax via Markstein, == __fdiv_rn
        float d  = xv - xmin;
        float q0 = d * rcpm;
        float e  = fmaf(-xmax, q0, d);
        float qq = fmaf(e, rcpm, q0);
        float t  = qq * 8.0f;                 // exact (power of two)
        int q = (int)t;                       // t >= 0 -> trunc == floor
        unsigned qc = (q < 8) ? (unsigned)q : 7u;
        unsigned fl = (q >= 8) ? 1u : 0u;
        return (__float_as_uint(xv) & ~0x780u) | (qc << 7) | (fl << 10);
    };

    // ---- channel-invariant prefetch geometry ----
    int  goff[KPT];
    int  soff[KPT];
    bool evalid[KPT];
#pragma unroll
    for (int k = 0; k < KPT; k++) {
        int e = tid + 128 * k;
        int r = e / 66;
        int c = e - r * 66;
        int gi = i0 - 1 + r;
        int gj = j0 - 1 + c;
        bool ok = (e < NELEM) && ((unsigned)gi < (unsigned)HB) &&
                  ((unsigned)gj < (unsigned)WB);
        goff[k]   = ok ? (gi * WB + gj) : 0;
        soff[k]   = r * PCOLS + c;
        evalid[k] = ok;
    }

    auto load_plane = [&](int cc, int buf) {   // prologue only
        unsigned* B = planes[buf];
        if ((unsigned)cc < (unsigned)CB) {
            const float* src = xb + cc * (HB * WB);
#pragma unroll
            for (int k = 0; k < KPT; k++) {
                if (tid + 128 * k < NELEM)
                    B[soff[k]] = evalid[k] ? pack(src[goff[k]]) : 0u;
            }
        } else {
#pragma unroll
            for (int k = 0; k < KPT; k++)
                if (tid + 128 * k < NELEM) B[soff[k]] = 0u;
        }
    };

    // prologue: planes -1,0,1,2 -> bufs 0..3  (plane p -> buf (p+1) & 7)
    load_plane(-1, 0);
    load_plane(0, 1);
    load_plane(1, 2);
    load_plane(2, 3);

    const int rowbase = 2 * wrp;
    const int gi0     = i0 + 2 * wrp;
    const int jb      = j0 + 2 * lane;
    const uint32_t lanebase = co_u32 + (lane << 2);

    auto tap3 = [&](float& acc, uint32_t rb, int fo,
                    unsigned p0, unsigned p1, unsigned p2) {
        acc = fmaf(fr[fo + 0], co_gather(p0, rb) * __uint_as_float(p0), acc);
        acc = fmaf(fr[fo + 1], co_gather(p1, rb) * __uint_as_float(p1), acc);
        acc = fmaf(fr[fo + 2], co_gather(p2, rb) * __uint_as_float(p2), acc);
    };

    for (int it = 0; it < CB / 2; it++) {
        const int ci   = 2 * it;
        const int base = (2 * it) & (NBUF - 1);   // buf of plane ci-1
        __syncthreads();

        // ---- stage LDGs for planes ci+3, ci+4 (no consumer until drain) ----
        float sv0[KPT], sv1[KPT];
        const bool do_pref = (it < CB / 2 - 1);
        if (do_pref) {
            const float* s0 = xb + (ci + 3) * (HB * WB);   // ci+3 <= 15 always
#pragma unroll
            for (int k = 0; k < KPT; k++)
                sv0[k] = evalid[k] ? s0[goff[k]] : 0.0f;
            if (ci + 4 < CB) {
                const float* s1 = xb + (ci + 4) * (HB * WB);
#pragma unroll
                for (int k = 0; k < KPT; k++)
                    sv1[k] = evalid[k] ? s1[goff[k]] : 0.0f;
            }
        }

        const int bA = (base + 1) & (NBUF - 1);   // plane ci
        const int bB = (base + 2) & (NBUF - 1);   // plane ci+1

        // ---- centers for both channels ----
        const unsigned* Pa = planes[bA] + rowbase * PCOLS + 2 * lane;
        const unsigned* Pb = planes[bB] + rowbase * PCOLS + 2 * lane;
        uint2 a1  = *(const uint2*)(Pa + 1 * PCOLS);
        uint2 a1h = *(const uint2*)(Pa + 1 * PCOLS + 2);
        uint2 a2  = *(const uint2*)(Pa + 2 * PCOLS);
        uint2 a2h = *(const uint2*)(Pa + 2 * PCOLS + 2);
        uint2 b1  = *(const uint2*)(Pb + 1 * PCOLS);
        uint2 b1h = *(const uint2*)(Pb + 1 * PCOLS + 2);
        uint2 b2  = *(const uint2*)(Pb + 2 * PCOLS);
        uint2 b2h = *(const uint2*)(Pb + 2 * PCOLS + 2);
        const unsigned cw00 = a1.y, cw01 = a1h.x, cw10 = a2.y, cw11 = a2h.x;
        const unsigned dw00 = b1.y, dw01 = b1h.x, dw10 = b2.y, dw11 = b2h.x;
        const uint32_t rb00 = lanebase + ((cw00 & 0x380u) << 3);
        const uint32_t rb01 = lanebase + ((cw01 & 0x380u) << 3);
        const uint32_t rb10 = lanebase + ((cw10 & 0x380u) << 3);
        const uint32_t rb11 = lanebase + ((cw11 & 0x380u) << 3);
        const uint32_t sb00 = lanebase + ((dw00 & 0x380u) << 3);
        const uint32_t sb01 = lanebase + ((dw01 & 0x380u) << 3);
        const uint32_t sb10 = lanebase + ((dw10 & 0x380u) << 3);
        const uint32_t sb11 = lanebase + ((dw11 & 0x380u) << 3);

        float a00 = 0.f, a01 = 0.f, a10 = 0.f, a11 = 0.f;   // channel ci
        float b00 = 0.f, b01 = 0.f, b10 = 0.f, b11 = 0.f;   // channel ci+1

#pragma unroll
        for (int pi = 0; pi < 4; pi++) {      // plane ci-1+pi
            const int bp = (base + pi) & (NBUF - 1);
            const unsigned* P = planes[bp] + rowbase * PCOLS + 2 * lane;
#pragma unroll
            for (int r = 0; r < 4; r++) {
                uint2 A  = *(const uint2*)(P + r * PCOLS);
                uint2 Bv = *(const uint2*)(P + r * PCOLS + 2);
                unsigned w0 = A.x, w1 = A.y, w2 = Bv.x, w3 = Bv.y;
                if (pi <= 2) {                 // channel ci, dc = pi
                    if (r <= 2) {
                        tap3(a00, rb00, pi * 9 + r * 3, w0, w1, w2);
                        tap3(a01, rb01, pi * 9 + r * 3, w1, w2, w3);
                    }
                    if (r >= 1) {
                        tap3(a10, rb10, pi * 9 + (r - 1) * 3, w0, w1, w2);
                        tap3(a11, rb11, pi * 9 + (r - 1) * 3, w1, w2, w3);
                    }
                }
                if (pi >= 1) {                 // channel ci+1, dc = pi-1
                    if (r <= 2) {
                        tap3(b00, sb00, (pi - 1) * 9 + r * 3, w0, w1, w2);
                        tap3(b01, sb01, (pi - 1) * 9 + r * 3, w1, w2, w3);
                    }
                    if (r >= 1) {
                        tap3(b10, sb10, (pi - 1) * 9 + (r - 1) * 3, w0, w1, w2);
                        tap3(b11, sb11, (pi - 1) * 9 + (r - 1) * 3, w1, w2, w3);
                    }
                }
            }
        }

        // ---- stores: channel ci ----
        const int o0 = ((n * CB + ci) * HB + gi0) * WB + jb;
        const int o1 = o0 + WB;
        {
            float2 r0v, r1v;
            r0v.x = (cw00 & 0x400u) ? 0.0f : a00;
            r0v.y = (cw01 & 0x400u) ? 0.0f : a01;
            r1v.x = (cw10 & 0x400u) ? 0.0f : a10;
            r1v.y = (cw11 & 0x400u) ? 0.0f : a11;
            *(float2*)(out + o0) = r0v;
            *(float2*)(out + o1) = r1v;
            out[IDX_OFF + o0]     = (float)(((cw00 >> 7) & 7u) + ((cw00 >> 10) & 1u));
            out[IDX_OFF + o0 + 1] = (float)(((cw01 >> 7) & 7u) + ((cw01 >> 10) & 1u));
            out[IDX_OFF + o1]     = (float)(((cw10 >> 7) & 7u) + ((cw10 >> 10) & 1u));
            out[IDX_OFF + o1 + 1] = (float)(((cw11 >> 7) & 7u) + ((cw11 >> 10) & 1u));
        }
        // ---- stores: channel ci+1 ----
        const int p0 = o0 + HB * WB;
        const int p1 = p0 + WB;
        {
            float2 r0v, r1v;
            r0v.x = (dw00 & 0x400u) ? 0.0f : b00;
            r0v.y = (dw01 & 0x400u) ? 0.0f : b01;
            r1v.x = (dw10 & 0x400u) ? 0.0f : b10;
            r1v.y = (dw11 & 0x400u) ? 0.0f : b11;
            *(float2*)(out + p0) = r0v;
            *(float2*)(out + p1) = r1v;
            out[IDX_OFF + p0]     = (float)(((dw00 >> 7) & 7u) + ((dw00 >> 10) & 1u));
            out[IDX_OFF + p0 + 1] = (float)(((dw01 >> 7) & 7u) + ((dw01 >> 10) & 1u));
            out[IDX_OFF + p1]     = (float)(((dw10 >> 7) & 7u) + ((dw10 >> 10) & 1u));
            out[IDX_OFF + p1 + 1] = (float)(((dw11 >> 7) & 7u) + ((dw11 >> 10) & 1u));
        }

        // ---- drain: pack staged values, store planes ci+3, ci+4 ----
        // writes hit bufs base+4, base+5: not read this iteration; next
        // iteration's reads happen after its top-of-loop __syncthreads.
        if (do_pref) {
            unsigned* B4 = planes[(base + 4) & (NBUF - 1)];
            unsigned* B5 = planes[(base + 5) & (NBUF - 1)];
            const bool in1 = (ci + 4 < CB);
#pragma unroll
            for (int k = 0; k < KPT; k++) {
                if (tid + 128 * k < NELEM) {
                    B4[soff[k]] = evalid[k] ? pack(sv0[k]) : 0u;
                    B5[soff[k]] = (in1 && evalid[k]) ? pack(sv1[k]) : 0u;
                }
            }
        }
    }
}

// ---------------------------------------------------------------------------
extern "C" void kernel_launch(void* const* d_in, const int* in_sizes, int n_in,
                              void* d_out, int out_size) {
    const float* x    = (const float*)d_in[0];
    const float* co   = (const float*)d_in[1];
    const float* filt = (const float*)d_in[2];
    float* out        = (float*)d_out;

    minmax_kernel<<<SLOTS, 256>>>((const float4*)x, TOT / 4, co, filt, out);

    dim3 grid(WB / TJ, HB / TI, NB);   // 4 x 32 x 8 = 1024 blocks
    cooc_kernel<<<grid, NTHR>>>(x, co, filt, out);
}

// round 15
// speedup vs baseline: 1.6841x; 1.0005x over previous
#include <cuda_runtime.h>
#include <cstdint>

#define NB 8
#define CB 16
#define HB 256
#define WB 256
#define TOT (NB*CB*HB*WB)   // 8388608
#define IDX_OFF (TOT + 91)

#define TJ 64               // output tile width  (j)
#define TI 8                // output tile height (i)
#define NTHR 128            // 4 warps; warp w -> output rows 2w, 2w+1
#define PCOLS 68            // 66 used (TJ+2 halo), padded
#define PROWS (TI+2)        // 10
#define PSZ (PROWS*PCOLS)
#define NELEM (PROWS*66)    // 660 plane elements
#define KPT 6               // ceil(660/128); k<5 always in range
#define NBUF 8              // power of two -> ring index is & 7
#define SLOTS 512

__device__ float2 g_mm[SLOTS];   // per-block (min,max) partials

// ---------------------------------------------------------------------------
__global__ void __launch_bounds__(256)
minmax_kernel(const float4* __restrict__ x, int n4,
              const float* __restrict__ co,
              const float* __restrict__ filt,
              float* __restrict__ out) {
    if (blockIdx.x == 0) {
        int t = threadIdx.x;
        if (t < 64) out[TOT + t] = co[t];
        if (t < 27) out[TOT + 64 + t] = filt[t];
    }
    float lmin = __int_as_float(0x7f800000);
    float lmax = 0.0f;
    int stride = gridDim.x * blockDim.x;
    for (int i = blockIdx.x * blockDim.x + threadIdx.x; i < n4; i += stride) {
        float4 v = x[i];
        lmin = fminf(lmin, fminf(fminf(v.x, v.y), fminf(v.z, v.w)));
        lmax = fmaxf(lmax, fmaxf(fmaxf(v.x, v.y), fmaxf(v.z, v.w)));
    }
#pragma unroll
    for (int o = 16; o; o >>= 1) {
        lmin = fminf(lmin, __shfl_xor_sync(0xffffffffu, lmin, o));
        lmax = fmaxf(lmax, __shfl_xor_sync(0xffffffffu, lmax, o));
    }
    __shared__ float smin[8], smax[8];
    int w = threadIdx.x >> 5;
    if ((threadIdx.x & 31) == 0) { smin[w] = lmin; smax[w] = lmax; }
    __syncthreads();
    if (threadIdx.x < 8) {
        lmin = smin[threadIdx.x];
        lmax = smax[threadIdx.x];
#pragma unroll
        for (int o = 4; o; o >>= 1) {
            lmin = fminf(lmin, __shfl_xor_sync(0xffu, lmin, o));
            lmax = fmaxf(lmax, __shfl_xor_sync(0xffu, lmax, o));
        }
        if (threadIdx.x == 0) g_mm[blockIdx.x] = make_float2(lmin, lmax);
    }
}

// ---------------------------------------------------------------------------
__device__ __forceinline__ uint32_t smem_u32(const void* p) {
    uint32_t a;
    asm("{ .reg .u64 t; cvta.to.shared.u64 t, %1; cvt.u32.u64 %0, t; }"
        : "=r"(a) : "l"(p));
    return a;
}

// co gather: addr = (w & 0x380) | rbase -> one LOP3, then LDS (bank = lane).
__device__ __forceinline__ float co_gather(uint32_t w, uint32_t rbase) {
    uint32_t a; float v;
    asm("lop3.b32 %0, %1, 0x380, %2, 0xEA;" : "=r"(a) : "r"(w), "r"(rbase));
    asm("ld.shared.f32 %0, [%1];" : "=f"(v) : "r"(a));
    return v;
}

// ---------------------------------------------------------------------------
// out[n,c,i,j] = [idx_p<8] * sum_{27} filt * co[idx_p, clamp(idx_nbr,7)] * x_nbr
//
// Packed word: x mantissa bits [9:7] = clamped column (pre-shifted byte
// offset for the 128B column stride), bit [10] = (idx==8) flag.
// co table: 8 rows x 8 cols x 32 lane replicas (8 KB), conflict-free.
//
// Quantization (bit-exact vs reference):
//  - Markstein exactly-rounded division (divisor xmax block-invariant)
//  - RZ floor-bit trick: u = fmaf_rz(qq, 8, 256); for v in [256,272) the
//    truncated mantissa bits [18:15] are floor(t); (u>>8)&0x780 is the
//    packed field directly, with ==0x400 -> 0x780 fixing the idx==8 case.
//
// Structure: TWO channels/iter, 8-buffer plane ring, staged-register LDGs
// hide global latency under compute; prologue also stages its 3 planes'
// LDGs before any pack consumes them.
// ---------------------------------------------------------------------------
__global__ void __launch_bounds__(NTHR)
cooc_kernel(const float* __restrict__ x,
            const float* __restrict__ co,
            const float* __restrict__ filt,
            float* __restrict__ out) {
    __shared__ __align__(16) unsigned planes[NBUF][PSZ];  // ~21.3 KB
    __shared__ float co_pad[2048 + 256];                  // 8 KB + align pad
    __shared__ float s_red[16];
    __shared__ float s_mm[2];

    const int tid  = threadIdx.x;
    const int lane = tid & 31;
    const int wrp  = tid >> 5;

    const int j0 = blockIdx.x * TJ;
    const int i0 = blockIdx.y * TI;
    const int n  = blockIdx.z;

    // ---- reduce min/max partials ----
    {
        float2 a = g_mm[tid];
        float2 b = g_mm[tid + 128];
        float2 c = g_mm[tid + 256];
        float2 d = g_mm[tid + 384];
        float mn = fminf(fminf(a.x, b.x), fminf(c.x, d.x));
        float mx = fmaxf(fmaxf(a.y, b.y), fmaxf(c.y, d.y));
#pragma unroll
        for (int o = 16; o; o >>= 1) {
            mn = fminf(mn, __shfl_xor_sync(0xffffffffu, mn, o));
            mx = fmaxf(mx, __shfl_xor_sync(0xffffffffu, mx, o));
        }
        if (lane == 0) { s_red[wrp] = mn; s_red[8 + wrp] = mx; }
    }

    // ---- replicated co LUT ----
    uintptr_t gp = (uintptr_t)co_pad;
    float* co_rep = (float*)((gp + 1023) & ~(uintptr_t)1023);
    const uint32_t co_u32 = smem_u32(co_rep);
    for (int e = tid; e < 2048; e += NTHR) {
        int l = e & 31;
        int c = (e >> 5) & 7;
        int r = e >> 8;
        co_rep[r * 256 + c * 32 + l] = co[r * 8 + c];
    }

    __syncthreads();
    if (tid < 2) {
        float v;
        if (tid == 0) v = fminf(fminf(s_red[0], s_red[1]), fminf(s_red[2], s_red[3]));
        else          v = fmaxf(fmaxf(s_red[8], s_red[9]), fmaxf(s_red[10], s_red[11]));
        s_mm[tid] = v;
    }
    __syncthreads();
    const float xmin = s_mm[0];
    const float xmax = s_mm[1];
    const float rcpm = __frcp_rn(xmax);   // RN(1/xmax), once per thread

    const float* xb = x + (size_t)n * (CB * HB * WB);

    auto pack = [&](float xv) -> unsigned {
        // exactly-rounded (x - xmin)/xmax (Markstein), then RZ floor bits
        float d  = xv - xmin;
        float q0 = d * rcpm;
        float e  = fmaf(-xmax, q0, d);
        float qq = fmaf(e, rcpm, q0);
        unsigned u = __float_as_uint(__fmaf_rz(qq, 8.0f, 256.0f));
        unsigned field = (u >> 8) & 0x780u;                 // q at [10:7]
        field = (field == 0x400u) ? 0x780u : field;          // q==8 -> col7+flag
        return (__float_as_uint(xv) & ~0x780u) | field;
    };

    // ---- channel-invariant prefetch geometry ----
    int  goff[KPT];
    int  soff[KPT];
    bool evalid[KPT];
#pragma unroll
    for (int k = 0; k < KPT; k++) {
        int e = tid + 128 * k;
        int r = e / 66;
        int c = e - r * 66;
        int gi = i0 - 1 + r;
        int gj = j0 - 1 + c;
        bool ok = (e < NELEM) && ((unsigned)gi < (unsigned)HB) &&
                  ((unsigned)gj < (unsigned)WB);
        goff[k]   = ok ? (gi * WB + gj) : 0;
        soff[k]   = r * PCOLS + c;
        evalid[k] = ok;
    }

    // ---- prologue: zero plane -1 (buf 0); stage LDGs for planes 0..2,
    //      then pack (hides 2 of 3 serial LDG latencies) ----
    {
        float s0[KPT], s1[KPT], s2[KPT];
#pragma unroll
        for (int k = 0; k < KPT; k++) {
            s0[k] = evalid[k] ? xb[goff[k]] : 0.0f;
            s1[k] = evalid[k] ? xb[1 * HB * WB + goff[k]] : 0.0f;
            s2[k] = evalid[k] ? xb[2 * HB * WB + goff[k]] : 0.0f;
        }
#pragma unroll
        for (int k = 0; k < KPT; k++) {
            if (k < 5 || tid + 128 * 5 < NELEM) {
                planes[0][soff[k]] = 0u;
                planes[1][soff[k]] = evalid[k] ? pack(s0[k]) : 0u;
                planes[2][soff[k]] = evalid[k] ? pack(s1[k]) : 0u;
                planes[3][soff[k]] = evalid[k] ? pack(s2[k]) : 0u;
            }
        }
    }

    // ---- filter -> registers (fenced); loaded after prologue to keep
    //      peak register pressure down ----
    float fr[27];
#pragma unroll
    for (int k = 0; k < 27; k++) {
        float v = filt[k];
        asm("mov.f32 %0, %0;" : "+f"(v));
        fr[k] = v;
    }

    const int rowbase = 2 * wrp;
    const int gi0     = i0 + 2 * wrp;
    const int jb      = j0 + 2 * lane;
    const uint32_t lanebase = co_u32 + (lane << 2);

    auto tap3 = [&](float& acc, uint32_t rb, int fo,
                    unsigned p0, unsigned p1, unsigned p2) {
        acc = fmaf(fr[fo + 0], co_gather(p0, rb) * __uint_as_float(p0), acc);
        acc = fmaf(fr[fo + 1], co_gather(p1, rb) * __uint_as_float(p1), acc);
        acc = fmaf(fr[fo + 2], co_gather(p2, rb) * __uint_as_float(p2), acc);
    };

#pragma unroll 1
    for (int it = 0; it < CB / 2; it++) {
        const int ci   = 2 * it;
        const int base = (2 * it) & (NBUF - 1);   // buf of plane ci-1
        __syncthreads();

        // ---- stage LDGs for planes ci+3, ci+4 (no consumer until drain) ----
        float sv0[KPT], sv1[KPT];
        const bool do_pref = (it < CB / 2 - 1);
        if (do_pref) {
            const float* s0 = xb + (ci + 3) * (HB * WB);   // ci+3 <= 15 always
#pragma unroll
            for (int k = 0; k < KPT; k++)
                sv0[k] = evalid[k] ? s0[goff[k]] : 0.0f;
            if (ci + 4 < CB) {
                const float* s1 = xb + (ci + 4) * (HB * WB);
#pragma unroll
                for (int k = 0; k < KPT; k++)
                    sv1[k] = evalid[k] ? s1[goff[k]] : 0.0f;
            }
        }

        const int bA = (base + 1) & (NBUF - 1);   // plane ci
        const int bB = (base + 2) & (NBUF - 1);   // plane ci+1

        // ---- centers for both channels ----
        const unsigned* Pa = planes[bA] + rowbase * PCOLS + 2 * lane;
        const unsigned* Pb = planes[bB] + rowbase * PCOLS + 2 * lane;
        uint2 a1  = *(const uint2*)(Pa + 1 * PCOLS);
        uint2 a1h = *(const uint2*)(Pa + 1 * PCOLS + 2);
        uint2 a2  = *(const uint2*)(Pa + 2 * PCOLS);
        uint2 a2h = *(const uint2*)(Pa + 2 * PCOLS + 2);
        uint2 b1  = *(const uint2*)(Pb + 1 * PCOLS);
        uint2 b1h = *(const uint2*)(Pb + 1 * PCOLS + 2);
        uint2 b2  = *(const uint2*)(Pb + 2 * PCOLS);
        uint2 b2h = *(const uint2*)(Pb + 2 * PCOLS + 2);
        const unsigned cw00 = a1.y, cw01 = a1h.x, cw10 = a2.y, cw11 = a2h.x;
        const unsigned dw00 = b1.y, dw01 = b1h.x, dw10 = b2.y, dw11 = b2h.x;
        const uint32_t rb00 = lanebase + ((cw00 & 0x380u) << 3);
        const uint32_t rb01 = lanebase + ((cw01 & 0x380u) << 3);
        const uint32_t rb10 = lanebase + ((cw10 & 0x380u) << 3);
        const uint32_t rb11 = lanebase + ((cw11 & 0x380u) << 3);
        const uint32_t sb00 = lanebase + ((dw00 & 0x380u) << 3);
        const uint32_t sb01 = lanebase + ((dw01 & 0x380u) << 3);
        const uint32_t sb10 = lanebase + ((dw10 & 0x380u) << 3);
        const uint32_t sb11 = lanebase + ((dw11 & 0x380u) << 3);

        float a00 = 0.f, a01 = 0.f, a10 = 0.f, a11 = 0.f;   // channel ci
        float b00 = 0.f, b01 = 0.f, b10 = 0.f, b11 = 0.f;   // channel ci+1

#pragma unroll
        for (int pi = 0; pi < 4; pi++) {      // plane ci-1+pi
            const int bp = (base + pi) & (NBUF - 1);
            const unsigned* P = planes[bp] + rowbase * PCOLS + 2 * lane;
#pragma unroll
            for (int r = 0; r < 4; r++) {
                uint2 A  = *(const uint2*)(P + r * PCOLS);
                uint2 Bv = *(const uint2*)(P + r * PCOLS + 2);
                unsigned w0 = A.x, w1 = A.y, w2 = Bv.x, w3 = Bv.y;
                if (pi <= 2) {                 // channel ci, dc = pi
                    if (r <= 2) {
                        tap3(a00, rb00, pi * 9 + r * 3, w0, w1, w2);
                        tap3(a01, rb01, pi * 9 + r * 3, w1, w2, w3);
                    }
                    if (r >= 1) {
                        tap3(a10, rb10, pi * 9 + (r - 1) * 3, w0, w1, w2);
                        tap3(a11, rb11, pi * 9 + (r - 1) * 3, w1, w2, w3);
                    }
                }
                if (pi >= 1) {                 // channel ci+1, dc = pi-1
                    if (r <= 2) {
                        tap3(b00, sb00, (pi - 1) * 9 + r * 3, w0, w1, w2);
                        tap3(b01, sb01, (pi - 1) * 9 + r * 3, w1, w2, w3);
                    }
                    if (r >= 1) {
                        tap3(b10, sb10, (pi - 1) * 9 + (r - 1) * 3, w0, w1, w2);
                        tap3(b11, sb11, (pi - 1) * 9 + (r - 1) * 3, w1, w2, w3);
                    }
                }
            }
        }

        // ---- stores: channel ci ----
        const int o0 = ((n * CB + ci) * HB + gi0) * WB + jb;
        const int o1 = o0 + WB;
        {
            float2 r0v, r1v;
            r0v.x = (cw00 & 0x400u) ? 0.0f : a00;
            r0v.y = (cw01 & 0x400u) ? 0.0f : a01;
            r1v.x = (cw10 & 0x400u) ? 0.0f : a10;
            r1v.y = (cw11 & 0x400u) ? 0.0f : a11;
            *(float2*)(out + o0) = r0v;
            *(float2*)(out + o1) = r1v;
            out[IDX_OFF + o0]     = (float)(((cw00 >> 7) & 7u) + ((cw00 >> 10) & 1u));
            out[IDX_OFF + o0 + 1] = (float)(((cw01 >> 7) & 7u) + ((cw01 >> 10) & 1u));
            out[IDX_OFF + o1]     = (float)(((cw10 >> 7) & 7u) + ((cw10 >> 10) & 1u));
            out[IDX_OFF + o1 + 1] = (float)(((cw11 >> 7) & 7u) + ((cw11 >> 10) & 1u));
        }
        // ---- stores: channel ci+1 ----
        const int p0 = o0 + HB * WB;
        const int p1 = p0 + WB;
        {
            float2 r0v, r1v;
            r0v.x = (dw00 & 0x400u) ? 0.0f : b00;
            r0v.y = (dw01 & 0x400u) ? 0.0f : b01;
            r1v.x = (dw10 & 0x400u) ? 0.0f : b10;
            r1v.y = (dw11 & 0x400u) ? 0.0f : b11;
            *(float2*)(out + p0) = r0v;
            *(float2*)(out + p1) = r1v;
            out[IDX_OFF + p0]     = (float)(((dw00 >> 7) & 7u) + ((dw00 >> 10) & 1u));
            out[IDX_OFF + p0 + 1] = (float)(((dw01 >> 7) & 7u) + ((dw01 >> 10) & 1u));
            out[IDX_OFF + p1]     = (float)(((dw10 >> 7) & 7u) + ((dw10 >> 10) & 1u));
            out[IDX_OFF + p1 + 1] = (float)(((dw11 >> 7) & 7u) + ((dw11 >> 10) & 1u));
        }

        // ---- drain: pack staged values, store planes ci+3, ci+4 ----
        // writes hit bufs base+4, base+5: not read this iteration; next
        // iteration's reads happen after its top-of-loop __syncthreads.
        if (do_pref) {
            unsigned* B4 = planes[(base + 4) & (NBUF - 1)];
            unsigned* B5 = planes[(base + 5) & (NBUF - 1)];
            const bool in1 = (ci + 4 < CB);
#pragma unroll
            for (int k = 0; k < KPT; k++) {
                if (k < 5 || tid + 128 * 5 < NELEM) {
                    B4[soff[k]] = evalid[k] ? pack(sv0[k]) : 0u;
                    B5[soff[k]] = (in1 && evalid[k]) ? pack(sv1[k]) : 0u;
                }
            }
        }
    }
}

// ---------------------------------------------------------------------------
extern "C" void kernel_launch(void* const* d_in, const int* in_sizes, int n_in,
                              void* d_out, int out_size) {
    const float* x    = (const float*)d_in[0];
    const float* co   = (const float*)d_in[1];
    const float* filt = (const float*)d_in[2];
    float* out        = (float*)d_out;

    minmax_kernel<<<SLOTS, 256>>>((const float4*)x, TOT / 4, co, filt, out);

    dim3 grid(WB / TJ, HB / TI, NB);   // 4 x 32 x 8 = 1024 blocks
    cooc_kernel<<<grid, NTHR>>>(x, co, filt, out);
}